// round 13
// baseline (speedup 1.0000x reference)
#include <cuda_runtime.h>
#include <cuda_fp16.h>

namespace {

constexpr int NS      = 512;     // matrix dim (S = K = O = 512)
constexpr int TM      = 32;      // block tile rows
constexpr int TN      = 64;      // block tile cols
constexpr int TK      = 64;      // k chunk (floats); 32 half2 pairs
constexpr int NCHUNK  = NS / TK; // 8
constexpr int THREADS = 128;     // 2 CTAs/SM
constexpr int KP      = TK / 2;  // 32 k-pairs per chunk
constexpr int ASTR    = KP + 4;  // As2 row stride (half2) = 36: multiple of 4 -> LDS.128 a-reads
                                 // 16B-aligned for every row; even -> STS.64 stores 8B-aligned

__global__ __launch_bounds__(THREADS, 2)
void fuzzy_compose_h2_kernel(const float* __restrict__ t, float* __restrict__ out)
{
    // A tile: [m][kpair] half2 = (A[m,2kp], A[m,2kp+1]), row stride 36 half2
    __shared__ __half2 As2[TM][ASTR];   // 4.6 KB
    // B tile: [kpair][n] half2 = (B[2kp,n], B[2kp+1,n])
    __shared__ __half2 Bs2[KP][TN];     // 8.2 KB

    const int comp = blockIdx.z;             // 0: t0∘t0, 1: t0∘t1
    const int bm   = blockIdx.y * TM;
    const int bn   = blockIdx.x * TN;

    const float* __restrict__ A = t;                     // t0 (left operand of both rules)
    const float* __restrict__ B = t + comp * (NS * NS);  // t[comp] (right operand)

    const int tid = threadIdx.x;
    const int tx  = tid & 15;       // n direction (16)
    const int ty  = tid >> 4;       // m direction (8)
    const int m0  = ty * 4;
    const int n0  = tx * 4;         // half2 columns == float columns

    // ---- loader indices ----
    const int lr = tid >> 4;        // 0..7 (A row base / B k-pair base)
    const int lc = (tid & 15) * 4;  // float column 0..60 (lc/2 even -> STS.64 aligned)

    __half2 acc[4][4];
    const __half2 h2zero = __float2half2_rn(0.0f);  // inputs in [0,1): 0 is max-identity
#pragma unroll
    for (int i = 0; i < 4; ++i)
#pragma unroll
        for (int j = 0; j < 4; ++j) acc[i][j] = h2zero;

    // ---- register prefetch of chunk 0 ----
    float4 ra0 = *reinterpret_cast<const float4*>(&A[(bm + lr     ) * NS + lc]);
    float4 ra1 = *reinterpret_cast<const float4*>(&A[(bm + lr +  8) * NS + lc]);
    float4 ra2 = *reinterpret_cast<const float4*>(&A[(bm + lr + 16) * NS + lc]);
    float4 ra3 = *reinterpret_cast<const float4*>(&A[(bm + lr + 24) * NS + lc]);
    float4 rb0e = *reinterpret_cast<const float4*>(&B[(2 * (lr     )    ) * NS + bn + lc]);
    float4 rb0o = *reinterpret_cast<const float4*>(&B[(2 * (lr     ) + 1) * NS + bn + lc]);
    float4 rb1e = *reinterpret_cast<const float4*>(&B[(2 * (lr +  8)    ) * NS + bn + lc]);
    float4 rb1o = *reinterpret_cast<const float4*>(&B[(2 * (lr +  8) + 1) * NS + bn + lc]);
    float4 rb2e = *reinterpret_cast<const float4*>(&B[(2 * (lr + 16)    ) * NS + bn + lc]);
    float4 rb2o = *reinterpret_cast<const float4*>(&B[(2 * (lr + 16) + 1) * NS + bn + lc]);
    float4 rb3e = *reinterpret_cast<const float4*>(&B[(2 * (lr + 24)    ) * NS + bn + lc]);
    float4 rb3o = *reinterpret_cast<const float4*>(&B[(2 * (lr + 24) + 1) * NS + bn + lc]);

    for (int c = 0; c < NCHUNK; ++c) {
        __syncthreads();   // previous chunk's compute done (no-op first iter)

        // A: float4 covers k..k+3 -> two k-adjacent half2; STS.64 per row
        {
            __half2 h0 = __floats2half2_rn(ra0.x, ra0.y);
            __half2 h1 = __floats2half2_rn(ra0.z, ra0.w);
            uint2 p; p.x = *reinterpret_cast<unsigned int*>(&h0);
                     p.y = *reinterpret_cast<unsigned int*>(&h1);
            *reinterpret_cast<uint2*>(&As2[lr][lc / 2]) = p;

            h0 = __floats2half2_rn(ra1.x, ra1.y);
            h1 = __floats2half2_rn(ra1.z, ra1.w);
            p.x = *reinterpret_cast<unsigned int*>(&h0);
            p.y = *reinterpret_cast<unsigned int*>(&h1);
            *reinterpret_cast<uint2*>(&As2[lr + 8][lc / 2]) = p;

            h0 = __floats2half2_rn(ra2.x, ra2.y);
            h1 = __floats2half2_rn(ra2.z, ra2.w);
            p.x = *reinterpret_cast<unsigned int*>(&h0);
            p.y = *reinterpret_cast<unsigned int*>(&h1);
            *reinterpret_cast<uint2*>(&As2[lr + 16][lc / 2]) = p;

            h0 = __floats2half2_rn(ra3.x, ra3.y);
            h1 = __floats2half2_rn(ra3.z, ra3.w);
            p.x = *reinterpret_cast<unsigned int*>(&h0);
            p.y = *reinterpret_cast<unsigned int*>(&h1);
            *reinterpret_cast<uint2*>(&As2[lr + 24][lc / 2]) = p;
        }
        // B: interleave even/odd k rows into (k,k+1) half2 per n col; STS.128
        {
            uint4 pk;
            __half2 b0 = __floats2half2_rn(rb0e.x, rb0o.x);
            __half2 b1 = __floats2half2_rn(rb0e.y, rb0o.y);
            __half2 b2 = __floats2half2_rn(rb0e.z, rb0o.z);
            __half2 b3 = __floats2half2_rn(rb0e.w, rb0o.w);
            pk.x = *reinterpret_cast<unsigned int*>(&b0);
            pk.y = *reinterpret_cast<unsigned int*>(&b1);
            pk.z = *reinterpret_cast<unsigned int*>(&b2);
            pk.w = *reinterpret_cast<unsigned int*>(&b3);
            *reinterpret_cast<uint4*>(&Bs2[lr][lc]) = pk;

            b0 = __floats2half2_rn(rb1e.x, rb1o.x);
            b1 = __floats2half2_rn(rb1e.y, rb1o.y);
            b2 = __floats2half2_rn(rb1e.z, rb1o.z);
            b3 = __floats2half2_rn(rb1e.w, rb1o.w);
            pk.x = *reinterpret_cast<unsigned int*>(&b0);
            pk.y = *reinterpret_cast<unsigned int*>(&b1);
            pk.z = *reinterpret_cast<unsigned int*>(&b2);
            pk.w = *reinterpret_cast<unsigned int*>(&b3);
            *reinterpret_cast<uint4*>(&Bs2[lr + 8][lc]) = pk;

            b0 = __floats2half2_rn(rb2e.x, rb2o.x);
            b1 = __floats2half2_rn(rb2e.y, rb2o.y);
            b2 = __floats2half2_rn(rb2e.z, rb2o.z);
            b3 = __floats2half2_rn(rb2e.w, rb2o.w);
            pk.x = *reinterpret_cast<unsigned int*>(&b0);
            pk.y = *reinterpret_cast<unsigned int*>(&b1);
            pk.z = *reinterpret_cast<unsigned int*>(&b2);
            pk.w = *reinterpret_cast<unsigned int*>(&b3);
            *reinterpret_cast<uint4*>(&Bs2[lr + 16][lc]) = pk;

            b0 = __floats2half2_rn(rb3e.x, rb3o.x);
            b1 = __floats2half2_rn(rb3e.y, rb3o.y);
            b2 = __floats2half2_rn(rb3e.z, rb3o.z);
            b3 = __floats2half2_rn(rb3e.w, rb3o.w);
            pk.x = *reinterpret_cast<unsigned int*>(&b0);
            pk.y = *reinterpret_cast<unsigned int*>(&b1);
            pk.z = *reinterpret_cast<unsigned int*>(&b2);
            pk.w = *reinterpret_cast<unsigned int*>(&b3);
            *reinterpret_cast<uint4*>(&Bs2[lr + 24][lc]) = pk;
        }
        __syncthreads();   // tiles visible

        if (c + 1 < NCHUNK) {
            const int kn = (c + 1) * TK;
            ra0 = *reinterpret_cast<const float4*>(&A[(bm + lr     ) * NS + kn + lc]);
            ra1 = *reinterpret_cast<const float4*>(&A[(bm + lr +  8) * NS + kn + lc]);
            ra2 = *reinterpret_cast<const float4*>(&A[(bm + lr + 16) * NS + kn + lc]);
            ra3 = *reinterpret_cast<const float4*>(&A[(bm + lr + 24) * NS + kn + lc]);
            rb0e = *reinterpret_cast<const float4*>(&B[(kn + 2 * (lr     )    ) * NS + bn + lc]);
            rb0o = *reinterpret_cast<const float4*>(&B[(kn + 2 * (lr     ) + 1) * NS + bn + lc]);
            rb1e = *reinterpret_cast<const float4*>(&B[(kn + 2 * (lr +  8)    ) * NS + bn + lc]);
            rb1o = *reinterpret_cast<const float4*>(&B[(kn + 2 * (lr +  8) + 1) * NS + bn + lc]);
            rb2e = *reinterpret_cast<const float4*>(&B[(kn + 2 * (lr + 16)    ) * NS + bn + lc]);
            rb2o = *reinterpret_cast<const float4*>(&B[(kn + 2 * (lr + 16) + 1) * NS + bn + lc]);
            rb3e = *reinterpret_cast<const float4*>(&B[(kn + 2 * (lr + 24)    ) * NS + bn + lc]);
            rb3o = *reinterpret_cast<const float4*>(&B[(kn + 2 * (lr + 24) + 1) * NS + bn + lc]);
        }

        // ---- compute: 4 k-pairs per sub-iteration, all smem reads LDS.128 ----
#pragma unroll
        for (int kq = 0; kq < KP; kq += 4) {
            // a rows m0..m0+3, k-pairs kq..kq+3 (ASTR=36 -> 16B-aligned)
            const uint4 av0 = *reinterpret_cast<const uint4*>(&As2[m0 + 0][kq]);
            const uint4 av1 = *reinterpret_cast<const uint4*>(&As2[m0 + 1][kq]);
            const uint4 av2 = *reinterpret_cast<const uint4*>(&As2[m0 + 2][kq]);
            const uint4 av3 = *reinterpret_cast<const uint4*>(&As2[m0 + 3][kq]);
            // b rows kq..kq+3 at n0
            const uint4 bv0 = *reinterpret_cast<const uint4*>(&Bs2[kq + 0][n0]);
            const uint4 bv1 = *reinterpret_cast<const uint4*>(&Bs2[kq + 1][n0]);
            const uint4 bv2 = *reinterpret_cast<const uint4*>(&Bs2[kq + 2][n0]);
            const uint4 bv3 = *reinterpret_cast<const uint4*>(&Bs2[kq + 3][n0]);

            const unsigned int aw[4][4] = {
                {av0.x, av0.y, av0.z, av0.w},
                {av1.x, av1.y, av1.z, av1.w},
                {av2.x, av2.y, av2.z, av2.w},
                {av3.x, av3.y, av3.z, av3.w}};
            const uint4 bw[4] = {bv0, bv1, bv2, bv3};

#pragma unroll
            for (int j = 0; j < 4; ++j) {
                const __half2 b0 = *reinterpret_cast<const __half2*>(&bw[j].x);
                const __half2 b1 = *reinterpret_cast<const __half2*>(&bw[j].y);
                const __half2 b2 = *reinterpret_cast<const __half2*>(&bw[j].z);
                const __half2 b3 = *reinterpret_cast<const __half2*>(&bw[j].w);
#pragma unroll
                for (int i = 0; i < 4; ++i) {
                    const __half2 a = *reinterpret_cast<const __half2*>(&aw[i][j]);
                    acc[i][0] = __hmax2(acc[i][0], __hmin2(a, b0));
                    acc[i][1] = __hmax2(acc[i][1], __hmin2(a, b1));
                    acc[i][2] = __hmax2(acc[i][2], __hmin2(a, b2));
                    acc[i][3] = __hmax2(acc[i][3], __hmin2(a, b3));
                }
            }
        }
    }

    // ---- epilogue: fold k-pair lanes, then out = t + num*(1 - t), t = t[comp] ----
    float* __restrict__ O = out + comp * (NS * NS);
#pragma unroll
    for (int i = 0; i < 4; ++i) {
        const int row = bm + m0 + i;
        const float4 tv = *reinterpret_cast<const float4*>(&B[row * NS + bn + n0]);
        float4 r;
        const float n00 = fmaxf(__low2float(acc[i][0]), __high2float(acc[i][0]));
        const float n01 = fmaxf(__low2float(acc[i][1]), __high2float(acc[i][1]));
        const float n02 = fmaxf(__low2float(acc[i][2]), __high2float(acc[i][2]));
        const float n03 = fmaxf(__low2float(acc[i][3]), __high2float(acc[i][3]));
        r.x = tv.x + n00 * (1.0f - tv.x);
        r.y = tv.y + n01 * (1.0f - tv.y);
        r.z = tv.z + n02 * (1.0f - tv.z);
        r.w = tv.w + n03 * (1.0f - tv.w);
        *reinterpret_cast<float4*>(&O[row * NS + bn + n0]) = r;
    }
}

} // namespace

extern "C" void kernel_launch(void* const* d_in, const int* in_sizes, int n_in,
                              void* d_out, int out_size)
{
    (void)in_sizes; (void)n_in; (void)out_size;
    const float* t = reinterpret_cast<const float*>(d_in[0]);
    float* out     = reinterpret_cast<float*>(d_out);

    dim3 grid(NS / TN, NS / TM, 2);   // 8 x 16 x 2 = 256 blocks, 2 CTAs/SM
    fuzzy_compose_h2_kernel<<<grid, THREADS>>>(t, out);
}

// round 14
// speedup vs baseline: 1.2092x; 1.2092x over previous
#include <cuda_runtime.h>
#include <cuda_fp16.h>

namespace {

constexpr int NS      = 512;     // matrix dim (S = K = O = 512)
constexpr int TM      = 16;      // block tile rows
constexpr int TN      = 64;      // block tile cols
constexpr int TK      = 64;      // k chunk (floats); 32 half2 pairs
constexpr int NCHUNK  = NS / TK; // 8
constexpr int THREADS = 128;     // target 4 CTAs/SM -> 16 warps/SM
constexpr int KP      = TK / 2;  // 32 k-pairs per chunk
constexpr int ASTR    = KP + 2;  // As2 row stride (half2) = 34: EVEN (STS.64 8B-aligned),
                                 // adjacent rows 2 banks apart -> conflict-free broadcast reads

__global__ __launch_bounds__(THREADS, 4)
void fuzzy_compose_h2_kernel(const float* __restrict__ t, float* __restrict__ out)
{
    // A tile: [m][kpair] half2 = (A[m,2kp], A[m,2kp+1]), row stride 34 half2
    __shared__ __half2 As2[TM][ASTR];   // 2.2 KB
    // B tile: [kpair][n] half2 = (B[2kp,n], B[2kp+1,n])
    __shared__ __half2 Bs2[KP][TN];     // 8.2 KB

    const int comp = blockIdx.z;             // 0: t0∘t0, 1: t0∘t1
    const int bm   = blockIdx.y * TM;
    const int bn   = blockIdx.x * TN;

    const float* __restrict__ A = t;                     // t0 (left operand of both rules)
    const float* __restrict__ B = t + comp * (NS * NS);  // t[comp] (right operand)

    const int tid = threadIdx.x;
    const int tx  = tid & 15;       // n direction (16)
    const int ty  = tid >> 4;       // m direction (8)
    const int m0  = ty * 2;
    const int n0  = tx * 4;         // half2 columns == float columns

    // ---- loader indices ----
    const int lr = tid >> 4;        // 0..7 (A row base / B k-pair base)
    const int lc = (tid & 15) * 4;  // float column 0..60 (lc/2 even -> STS.64 aligned)

    __half2 acc[2][4];
    const __half2 h2zero = __float2half2_rn(0.0f);  // inputs in [0,1): 0 is max-identity
#pragma unroll
    for (int i = 0; i < 2; ++i)
#pragma unroll
        for (int j = 0; j < 4; ++j) acc[i][j] = h2zero;

    // ---- register prefetch of chunk 0 ----
    // A tile 16 rows x 64 cols: rows lr, lr+8
    float4 ra0 = *reinterpret_cast<const float4*>(&A[(bm + lr    ) * NS + lc]);
    float4 ra1 = *reinterpret_cast<const float4*>(&A[(bm + lr + 8) * NS + lc]);
    // B tile 64 k-rows x 64 cols: k-pairs lr, lr+8, lr+16, lr+24 (even/odd rows)
    float4 rb0e = *reinterpret_cast<const float4*>(&B[(2 * (lr     )    ) * NS + bn + lc]);
    float4 rb0o = *reinterpret_cast<const float4*>(&B[(2 * (lr     ) + 1) * NS + bn + lc]);
    float4 rb1e = *reinterpret_cast<const float4*>(&B[(2 * (lr +  8)    ) * NS + bn + lc]);
    float4 rb1o = *reinterpret_cast<const float4*>(&B[(2 * (lr +  8) + 1) * NS + bn + lc]);
    float4 rb2e = *reinterpret_cast<const float4*>(&B[(2 * (lr + 16)    ) * NS + bn + lc]);
    float4 rb2o = *reinterpret_cast<const float4*>(&B[(2 * (lr + 16) + 1) * NS + bn + lc]);
    float4 rb3e = *reinterpret_cast<const float4*>(&B[(2 * (lr + 24)    ) * NS + bn + lc]);
    float4 rb3o = *reinterpret_cast<const float4*>(&B[(2 * (lr + 24) + 1) * NS + bn + lc]);

    for (int c = 0; c < NCHUNK; ++c) {
        __syncthreads();   // previous chunk's compute done (no-op first iter)

        // A: float4 covers k..k+3 -> two k-adjacent half2; STS.64 per row
        {
            __half2 h0 = __floats2half2_rn(ra0.x, ra0.y);
            __half2 h1 = __floats2half2_rn(ra0.z, ra0.w);
            uint2 p; p.x = *reinterpret_cast<unsigned int*>(&h0);
                     p.y = *reinterpret_cast<unsigned int*>(&h1);
            *reinterpret_cast<uint2*>(&As2[lr][lc / 2]) = p;

            h0 = __floats2half2_rn(ra1.x, ra1.y);
            h1 = __floats2half2_rn(ra1.z, ra1.w);
            p.x = *reinterpret_cast<unsigned int*>(&h0);
            p.y = *reinterpret_cast<unsigned int*>(&h1);
            *reinterpret_cast<uint2*>(&As2[lr + 8][lc / 2]) = p;
        }
        // B: interleave even/odd k rows into (k,k+1) half2 per n col; STS.128
        {
            uint4 pk;
            __half2 b0 = __floats2half2_rn(rb0e.x, rb0o.x);
            __half2 b1 = __floats2half2_rn(rb0e.y, rb0o.y);
            __half2 b2 = __floats2half2_rn(rb0e.z, rb0o.z);
            __half2 b3 = __floats2half2_rn(rb0e.w, rb0o.w);
            pk.x = *reinterpret_cast<unsigned int*>(&b0);
            pk.y = *reinterpret_cast<unsigned int*>(&b1);
            pk.z = *reinterpret_cast<unsigned int*>(&b2);
            pk.w = *reinterpret_cast<unsigned int*>(&b3);
            *reinterpret_cast<uint4*>(&Bs2[lr][lc]) = pk;

            b0 = __floats2half2_rn(rb1e.x, rb1o.x);
            b1 = __floats2half2_rn(rb1e.y, rb1o.y);
            b2 = __floats2half2_rn(rb1e.z, rb1o.z);
            b3 = __floats2half2_rn(rb1e.w, rb1o.w);
            pk.x = *reinterpret_cast<unsigned int*>(&b0);
            pk.y = *reinterpret_cast<unsigned int*>(&b1);
            pk.z = *reinterpret_cast<unsigned int*>(&b2);
            pk.w = *reinterpret_cast<unsigned int*>(&b3);
            *reinterpret_cast<uint4*>(&Bs2[lr + 8][lc]) = pk;

            b0 = __floats2half2_rn(rb2e.x, rb2o.x);
            b1 = __floats2half2_rn(rb2e.y, rb2o.y);
            b2 = __floats2half2_rn(rb2e.z, rb2o.z);
            b3 = __floats2half2_rn(rb2e.w, rb2o.w);
            pk.x = *reinterpret_cast<unsigned int*>(&b0);
            pk.y = *reinterpret_cast<unsigned int*>(&b1);
            pk.z = *reinterpret_cast<unsigned int*>(&b2);
            pk.w = *reinterpret_cast<unsigned int*>(&b3);
            *reinterpret_cast<uint4*>(&Bs2[lr + 16][lc]) = pk;

            b0 = __floats2half2_rn(rb3e.x, rb3o.x);
            b1 = __floats2half2_rn(rb3e.y, rb3o.y);
            b2 = __floats2half2_rn(rb3e.z, rb3o.z);
            b3 = __floats2half2_rn(rb3e.w, rb3o.w);
            pk.x = *reinterpret_cast<unsigned int*>(&b0);
            pk.y = *reinterpret_cast<unsigned int*>(&b1);
            pk.z = *reinterpret_cast<unsigned int*>(&b2);
            pk.w = *reinterpret_cast<unsigned int*>(&b3);
            *reinterpret_cast<uint4*>(&Bs2[lr + 24][lc]) = pk;
        }
        __syncthreads();   // tiles visible

        if (c + 1 < NCHUNK) {
            const int kn = (c + 1) * TK;
            ra0 = *reinterpret_cast<const float4*>(&A[(bm + lr    ) * NS + kn + lc]);
            ra1 = *reinterpret_cast<const float4*>(&A[(bm + lr + 8) * NS + kn + lc]);
            rb0e = *reinterpret_cast<const float4*>(&B[(kn + 2 * (lr     )    ) * NS + bn + lc]);
            rb0o = *reinterpret_cast<const float4*>(&B[(kn + 2 * (lr     ) + 1) * NS + bn + lc]);
            rb1e = *reinterpret_cast<const float4*>(&B[(kn + 2 * (lr +  8)    ) * NS + bn + lc]);
            rb1o = *reinterpret_cast<const float4*>(&B[(kn + 2 * (lr +  8) + 1) * NS + bn + lc]);
            rb2e = *reinterpret_cast<const float4*>(&B[(kn + 2 * (lr + 16)    ) * NS + bn + lc]);
            rb2o = *reinterpret_cast<const float4*>(&B[(kn + 2 * (lr + 16) + 1) * NS + bn + lc]);
            rb3e = *reinterpret_cast<const float4*>(&B[(kn + 2 * (lr + 24)    ) * NS + bn + lc]);
            rb3o = *reinterpret_cast<const float4*>(&B[(kn + 2 * (lr + 24) + 1) * NS + bn + lc]);
        }

#pragma unroll
        for (int kp = 0; kp < KP; ++kp) {
            const __half2 a0 = As2[m0 + 0][kp];
            const __half2 a1 = As2[m0 + 1][kp];

            const uint4 bv = *reinterpret_cast<const uint4*>(&Bs2[kp][n0]);
            const __half2 b0 = *reinterpret_cast<const __half2*>(&bv.x);
            const __half2 b1 = *reinterpret_cast<const __half2*>(&bv.y);
            const __half2 b2 = *reinterpret_cast<const __half2*>(&bv.z);
            const __half2 b3 = *reinterpret_cast<const __half2*>(&bv.w);

            acc[0][0] = __hmax2(acc[0][0], __hmin2(a0, b0));
            acc[0][1] = __hmax2(acc[0][1], __hmin2(a0, b1));
            acc[0][2] = __hmax2(acc[0][2], __hmin2(a0, b2));
            acc[0][3] = __hmax2(acc[0][3], __hmin2(a0, b3));

            acc[1][0] = __hmax2(acc[1][0], __hmin2(a1, b0));
            acc[1][1] = __hmax2(acc[1][1], __hmin2(a1, b1));
            acc[1][2] = __hmax2(acc[1][2], __hmin2(a1, b2));
            acc[1][3] = __hmax2(acc[1][3], __hmin2(a1, b3));
        }
    }

    // ---- epilogue: fold k-pair lanes, then out = t + num*(1 - t), t = t[comp] ----
    float* __restrict__ O = out + comp * (NS * NS);
#pragma unroll
    for (int i = 0; i < 2; ++i) {
        const int row = bm + m0 + i;
        const float4 tv = *reinterpret_cast<const float4*>(&B[row * NS + bn + n0]);
        float4 r;
        const float n00 = fmaxf(__low2float(acc[i][0]), __high2float(acc[i][0]));
        const float n01 = fmaxf(__low2float(acc[i][1]), __high2float(acc[i][1]));
        const float n02 = fmaxf(__low2float(acc[i][2]), __high2float(acc[i][2]));
        const float n03 = fmaxf(__low2float(acc[i][3]), __high2float(acc[i][3]));
        r.x = tv.x + n00 * (1.0f - tv.x);
        r.y = tv.y + n01 * (1.0f - tv.y);
        r.z = tv.z + n02 * (1.0f - tv.z);
        r.w = tv.w + n03 * (1.0f - tv.w);
        *reinterpret_cast<float4*>(&O[row * NS + bn + n0]) = r;
    }
}

} // namespace

extern "C" void kernel_launch(void* const* d_in, const int* in_sizes, int n_in,
                              void* d_out, int out_size)
{
    (void)in_sizes; (void)n_in; (void)out_size;
    const float* t = reinterpret_cast<const float*>(d_in[0]);
    float* out     = reinterpret_cast<float*>(d_out);

    dim3 grid(NS / TN, NS / TM, 2);   // 8 x 32 x 2 = 512 blocks, 4 CTAs/SM
    fuzzy_compose_h2_kernel<<<grid, THREADS>>>(t, out);
}